// round 9
// baseline (speedup 1.0000x reference)
#include <cuda_runtime.h>
#include <cuda_bf16.h>
#include <cstdint>

#define B 8
#define C 128
#define HW 65536
#define K 64
#define NTOT 524288.0f
#define BN_EPS 1e-5f

// ---------------- scratch (device globals; no allocation allowed) ----------------
__device__ float g_G[C * C];                    // Gram matrix sum_p x x^T
__device__ float g_sums_x[B * K * C];           // segment sums of x
__device__ float g_cnt[B * K];                  // segment counts
__device__ float g_sumsq[C];                    // per-channel sum of xw^2
__device__ float g_means[B * K * C];
__device__ float g_M[C * C];                    // W @ W^T
__device__ float g_Y[B * K * C];                // means @ M
__device__ float g_adj[B * K * K];
__device__ float g_adjm[B * K * C];             // adj_nd @ means
__device__ float g_s[C];
__device__ float g_t[C];
__device__ __nv_bfloat16 g_wh[C * 132];         // w^T hi  [d][c], pitch 132
__device__ __nv_bfloat16 g_wl[C * 132];         // w^T lo

#define MMA_BF16(d, a, bb) \
    asm volatile("mma.sync.aligned.m16n8k16.row.col.f32.bf16.bf16.f32 " \
        "{%0,%1,%2,%3}, {%4,%5,%6,%7}, {%8,%9}, {%0,%1,%2,%3};" \
        : "+f"((d)[0]), "+f"((d)[1]), "+f"((d)[2]), "+f"((d)[3]) \
        : "r"((a)[0]), "r"((a)[1]), "r"((a)[2]), "r"((a)[3]), \
          "r"((bb)[0]), "r"((bb)[1]))

__device__ __forceinline__ uint32_t smem_u32(const void* p) {
    uint32_t a;
    asm("{ .reg .u64 t; cvta.to.shared.u64 t, %1; cvt.u32.u64 %0, t; }" : "=r"(a) : "l"(p));
    return a;
}
__device__ __forceinline__ void ldsm_x4_trans(uint32_t& r0, uint32_t& r1,
                                              uint32_t& r2, uint32_t& r3, uint32_t addr) {
    asm volatile("ldmatrix.sync.aligned.m8n8.x4.trans.shared.b16 {%0,%1,%2,%3}, [%4];"
                 : "=r"(r0), "=r"(r1), "=r"(r2), "=r"(r3) : "r"(addr));
}

// ---------------- kernel 0: zero accumulators ----------------
__global__ void k_zero() {
    int i = blockIdx.x * blockDim.x + threadIdx.x;
    if (i < B * K * C) g_sums_x[i] = 0.f;
    if (i < C * C)     g_G[i] = 0.f;
    if (i < B * K)     g_cnt[i] = 0.f;
}

// ---------------- kernel 0.5: prep w^T hi/lo ----------------
__global__ void k_wprep(const float* __restrict__ w) {
    int i = blockIdx.x * 256 + threadIdx.x;
    if (i < C * C) {
        int c = i >> 7, d = i & 127;
        float v = w[i];
        __nv_bfloat16 h = __float2bfloat16(v);
        g_wh[d * 132 + c] = h;
        g_wl[d * 132 + c] = __float2bfloat16(v - __bfloat162float(h));
    }
}

// ================= kernel 1: fused stats pass (G, segment sums, counts) =================
// grid 144 (8 b x 18 walkers), 256 threads; each block walks chunks j, j+18, ... (<512)
#define P1_PITCH 132
#define P1_XH 0
#define P1_XL 33792
#define P1_OH 67584
#define P1_TOTAL 84480

__global__ __launch_bounds__(256, 1) void k_pass1(const float* __restrict__ x,
                                                  const int* __restrict__ idx) {
    extern __shared__ char smem[];
    __nv_bfloat16* Xh = (__nv_bfloat16*)(smem + P1_XH);
    __nv_bfloat16* Xl = (__nv_bfloat16*)(smem + P1_XL);
    __nv_bfloat16* OH = (__nv_bfloat16*)(smem + P1_OH);
    __shared__ int   sidx[128];
    __shared__ float hcnt[K];

    int tid = threadIdx.x;
    int b   = blockIdx.x / 18;
    int j   = blockIdx.x % 18;
    int lane = tid & 31, wid = tid >> 5;
    int gid = lane >> 2, tig = lane & 3;
    int dbase  = (wid & 3) * 32;    // G m-tile (rows c1)
    int msbase = (wid & 3) * 16;    // S m-tile (rows k)
    int pbase  = (wid >> 2) * 64;   // n-half (cols c2 / c)

    if (tid < K) hcnt[tid] = 0.f;

    float Dg[2][8][4];
    float Ds[8][4];
#pragma unroll
    for (int mf = 0; mf < 2; mf++)
#pragma unroll
        for (int nf = 0; nf < 8; nf++)
#pragma unroll
            for (int q = 0; q < 4; q++) Dg[mf][nf][q] = 0.f;
#pragma unroll
    for (int nf = 0; nf < 8; nf++)
#pragma unroll
        for (int q = 0; q < 4; q++) Ds[nf][q] = 0.f;

    const float* xb = x + (size_t)b * C * HW;
    const int*   ib = idx + b * HW;

    for (int ch = j; ch < 512; ch += 18) {
        __syncthreads();
        if (tid < 128) sidx[tid] = ib[ch * 128 + tid];
        for (int i = tid; i < 4224; i += 256) ((uint32_t*)OH)[i] = 0u;
        for (int e = tid; e < 4096; e += 256) {
            int row = e >> 5, p4 = (e & 31) * 4;
            float4 v = *(const float4*)(xb + (size_t)row * HW + ch * 128 + p4);
            __nv_bfloat162 h0 = __floats2bfloat162_rn(v.x, v.y);
            __nv_bfloat162 h1 = __floats2bfloat162_rn(v.z, v.w);
            float l0 = v.x - __bfloat162float(h0.x);
            float l1 = v.y - __bfloat162float(h0.y);
            float l2 = v.z - __bfloat162float(h1.x);
            float l3 = v.w - __bfloat162float(h1.y);
            __nv_bfloat162 g0 = __floats2bfloat162_rn(l0, l1);
            __nv_bfloat162 g1 = __floats2bfloat162_rn(l2, l3);
            *(__nv_bfloat162*)&Xh[row * P1_PITCH + p4]     = h0;
            *(__nv_bfloat162*)&Xh[row * P1_PITCH + p4 + 2] = h1;
            *(__nv_bfloat162*)&Xl[row * P1_PITCH + p4]     = g0;
            *(__nv_bfloat162*)&Xl[row * P1_PITCH + p4 + 2] = g1;
        }
        __syncthreads();
        if (tid < 128) {
            int k = sidx[tid];
            OH[k * P1_PITCH + tid] = __float2bfloat16(1.0f);
            atomicAdd(&hcnt[k], 1.f);
        }
        __syncthreads();

#pragma unroll
        for (int ks = 0; ks < 8; ks++) {
            int k0 = ks * 16;
            uint32_t bh[8][2], bl[8][2];
#pragma unroll
            for (int nf = 0; nf < 8; nf++) {
                int cn = pbase + nf * 8 + gid;
                bh[nf][0] = *(const uint32_t*)&Xh[cn * P1_PITCH + k0 + 2 * tig];
                bh[nf][1] = *(const uint32_t*)&Xh[cn * P1_PITCH + k0 + 8 + 2 * tig];
                bl[nf][0] = *(const uint32_t*)&Xl[cn * P1_PITCH + k0 + 2 * tig];
                bl[nf][1] = *(const uint32_t*)&Xl[cn * P1_PITCH + k0 + 8 + 2 * tig];
            }
            uint32_t ah[2][4];
#pragma unroll
            for (int mf = 0; mf < 2; mf++) {
                int r0 = dbase + mf * 16 + gid;
                ah[mf][0] = *(const uint32_t*)&Xh[r0 * P1_PITCH + k0 + 2 * tig];
                ah[mf][1] = *(const uint32_t*)&Xh[(r0 + 8) * P1_PITCH + k0 + 2 * tig];
                ah[mf][2] = *(const uint32_t*)&Xh[r0 * P1_PITCH + k0 + 8 + 2 * tig];
                ah[mf][3] = *(const uint32_t*)&Xh[(r0 + 8) * P1_PITCH + k0 + 8 + 2 * tig];
            }
            uint32_t ao[4];
            {
                int m0 = msbase + gid;
                ao[0] = *(const uint32_t*)&OH[m0 * P1_PITCH + k0 + 2 * tig];
                ao[1] = *(const uint32_t*)&OH[(m0 + 8) * P1_PITCH + k0 + 2 * tig];
                ao[2] = *(const uint32_t*)&OH[m0 * P1_PITCH + k0 + 8 + 2 * tig];
                ao[3] = *(const uint32_t*)&OH[(m0 + 8) * P1_PITCH + k0 + 8 + 2 * tig];
            }
#pragma unroll
            for (int mf = 0; mf < 2; mf++)
#pragma unroll
                for (int nf = 0; nf < 8; nf++)
                    MMA_BF16(Dg[mf][nf], ah[mf], bh[nf]);
#pragma unroll
            for (int nf = 0; nf < 8; nf++) {
                MMA_BF16(Ds[nf], ao, bh[nf]);
                MMA_BF16(Ds[nf], ao, bl[nf]);
            }
        }
    }

    // ---- flush partials ----
#pragma unroll
    for (int mf = 0; mf < 2; mf++)
#pragma unroll
        for (int nf = 0; nf < 8; nf++) {
            int r0 = dbase + mf * 16 + gid;
            int cn = pbase + nf * 8 + 2 * tig;
            atomicAdd(&g_G[r0 * C + cn],           Dg[mf][nf][0]);
            atomicAdd(&g_G[r0 * C + cn + 1],       Dg[mf][nf][1]);
            atomicAdd(&g_G[(r0 + 8) * C + cn],     Dg[mf][nf][2]);
            atomicAdd(&g_G[(r0 + 8) * C + cn + 1], Dg[mf][nf][3]);
        }
#pragma unroll
    for (int nf = 0; nf < 8; nf++) {
        int m0 = msbase + gid;
        int cn = pbase + nf * 8 + 2 * tig;
        atomicAdd(&g_sums_x[(b * K + m0) * C + cn],           Ds[nf][0]);
        atomicAdd(&g_sums_x[(b * K + m0) * C + cn + 1],       Ds[nf][1]);
        atomicAdd(&g_sums_x[(b * K + m0 + 8) * C + cn],       Ds[nf][2]);
        atomicAdd(&g_sums_x[(b * K + m0 + 8) * C + cn + 1],   Ds[nf][3]);
    }
    __syncthreads();
    if (tid < K) atomicAdd(&g_cnt[b * K + tid], hcnt[tid]);
}

// ---------------- kernel A: fused M=WW^T | sumsq=w^T G w | means ----------------
// grid 768, 128 threads: [0,128) M rows; [128,256) sumsq d; [256,768) means bk
__global__ void kA(const float* __restrict__ w, const float* __restrict__ Wm) {
    int blk = blockIdx.x;
    int t = threadIdx.x;
    if (blk < 128) {
        __shared__ float wi[C];
        int i = blk;
        wi[t] = Wm[i * C + t];
        __syncthreads();
        float acc = 0.f;
#pragma unroll 8
        for (int c = 0; c < C; c++) acc += wi[c] * Wm[t * C + c];
        g_M[i * C + t] = acc;
    } else if (blk < 256) {
        __shared__ float wcol[C];
        __shared__ float red[C];
        int d = blk - 128;
        wcol[t] = w[t * C + d];
        __syncthreads();
        float acc = 0.f;
#pragma unroll 8
        for (int c2 = 0; c2 < C; c2++) acc += g_G[t * C + c2] * wcol[c2];
        red[t] = acc * wcol[t];
        __syncthreads();
        for (int s = 64; s > 0; s >>= 1) {
            if (t < s) red[t] += red[t + s];
            __syncthreads();
        }
        if (t == 0) g_sumsq[d] = red[0];
    } else {
        __shared__ float s[C];
        int bk = blk - 256;
        s[t] = g_sums_x[bk * C + t];
        __syncthreads();
        float cnt = g_cnt[bk];
        float denom = (cnt == 0.f) ? 1.f : cnt;
        float acc = 0.f;
#pragma unroll 8
        for (int c = 0; c < C; c++) acc += s[c] * w[c * C + t];
        g_means[bk * C + t] = acc / denom;
    }
}

// ---------------- kernel 5: Y[b,k,d] = means[b,k,:] @ M ----------------
__global__ void k_Y() {
    __shared__ float ms[C];
    int bk = blockIdx.x;
    int d = threadIdx.x;
    ms[d] = g_means[bk * C + d];
    __syncthreads();
    float acc = 0.f;
#pragma unroll 8
    for (int c = 0; c < C; c++) acc += ms[c] * g_M[c * C + d];
    g_Y[bk * C + d] = acc;
}

// ---------------- kernel 6: adjacency + adj_means ----------------
__global__ __launch_bounds__(256) void k_adj(const float* __restrict__ adj_mask) {
    __shared__ float msm[K][C + 1];
    __shared__ float gq[K];
    int b = blockIdx.x, tid = threadIdx.x;
    const float* mb = g_means + b * K * C;
    const float* yb = g_Y + b * K * C;

    for (int i = tid; i < K * C; i += 256) msm[i >> 7][i & 127] = mb[i];
    __syncthreads();

    if (tid < K) {
        float a = 0.f;
#pragma unroll 8
        for (int d = 0; d < C; d++) a += yb[tid * C + d] * msm[tid][d];
        gq[tid] = a;
    }
    __syncthreads();

    for (int i = tid; i < K * K; i += 256) {
        int p = i >> 6, q = i & 63;
        float dot = 0.f;
#pragma unroll 8
        for (int d = 0; d < C; d++) dot += yb[p * C + d] * msm[q][d];
        float quad = gq[p] + gq[q] - 2.f * dot;
        g_adj[b * K * K + i] = (p == q) ? 0.f : expf(-quad) * adj_mask[i];
    }
    __syncthreads();

    for (int i = tid; i < K * C; i += 256) {
        int p = i >> 7, d = i & 127;
        const float* arow = g_adj + b * K * K + p * K;
        float acc = 0.f;
#pragma unroll 8
        for (int q = 0; q < K; q++) acc += arow[q] * msm[q][d];
        g_adjm[b * K * C + i] = acc;
    }
}

// ---------------- kernel 7: BN statistics (analytic) ----------------
__global__ void k_bnstats(const float* __restrict__ gamma, const float* __restrict__ beta) {
    int d = threadIdx.x;
    float S1 = 0.f, S2 = 0.f;
    for (int bk = 0; bk < B * K; bk++) {
        float cnt = g_cnt[bk];
        float denom = (cnt == 0.f) ? 1.f : cnt;
        float m = g_means[bk * C + d];
        float am = g_adjm[bk * C + d];
        float sxw = m * denom;
        S1 += sxw + cnt * am;
        S2 += 2.f * am * sxw + cnt * am * am;
    }
    S2 += g_sumsq[d];
    float mu = S1 / NTOT;
    float var = S2 / NTOT - mu * mu;
    float s = gamma[d] * rsqrtf(var + BN_EPS);
    g_s[d] = s;
    g_t[d] = beta[d] - mu * s;
}

// ================= kernel 9: fused GEMM + output (ldmatrix.trans path) =================
// out[b,d,p] = s[d] * (x @ weight)[b,d,p] + (s[d]*adjm[b,idx[p],d] + t[d])
// A (w^T hi/lo) copied prepped from global; X stored [c][p] bf16 hi/lo, B-fragments
// loaded via ldmatrix.m8n8.x4.trans (no fp32 staging transpose).
#define A_PITCH 132
#define X_PITCH 136
#define GSM2_AH 0
#define GSM2_AL 33792
#define GSM2_XH 67584
#define GSM2_XL 102400
#define GSM2_TOTAL 137216

__global__ __launch_bounds__(256, 1) void k_gemm_out(const float* __restrict__ x,
                                                     const int* __restrict__ idx,
                                                     float* __restrict__ out) {
    extern __shared__ char smem[];
    __nv_bfloat16* Ah = (__nv_bfloat16*)(smem + GSM2_AH);
    __nv_bfloat16* Al = (__nv_bfloat16*)(smem + GSM2_AL);
    __nv_bfloat16* Xh = (__nv_bfloat16*)(smem + GSM2_XH);
    __nv_bfloat16* Xl = (__nv_bfloat16*)(smem + GSM2_XL);
    float* estage = (float*)smem;                 // epilogue alias over Ah+Al (67584 B)
    float* bsm    = (float*)(smem + GSM2_XH);     // epilogue alias over Xh (32768 B used)
    __shared__ float ssm[C], tsm[C];
    __shared__ int   sidxp[128];

    int tid = threadIdx.x;
    int b = blockIdx.x >> 9;
    int p0 = (blockIdx.x & 511) << 7;
    const float* xb = x + (size_t)b * C * HW + p0;

    if (tid < 128) sidxp[tid] = idx[b * HW + p0 + tid];
    if (tid < C) { ssm[tid] = g_s[tid]; tsm[tid] = g_t[tid]; }

    // ---- copy prepped W hi/lo ----
    {
        const uint32_t* wh32 = (const uint32_t*)g_wh;
        const uint32_t* wl32 = (const uint32_t*)g_wl;
        uint32_t* ah32 = (uint32_t*)Ah;
        uint32_t* al32 = (uint32_t*)Al;
        for (int i = tid; i < 8448; i += 256) { ah32[i] = wh32[i]; al32[i] = wl32[i]; }
    }
    // ---- convert x -> [c][p] bf16 hi/lo (coalesced both sides, no transpose) ----
    for (int e = tid; e < 4096; e += 256) {
        int row = e >> 5, p4 = (e & 31) * 4;
        float4 v = *(const float4*)(xb + (size_t)row * HW + p4);
        __nv_bfloat162 h0 = __floats2bfloat162_rn(v.x, v.y);
        __nv_bfloat162 h1 = __floats2bfloat162_rn(v.z, v.w);
        float l0 = v.x - __bfloat162float(h0.x);
        float l1 = v.y - __bfloat162float(h0.y);
        float l2 = v.z - __bfloat162float(h1.x);
        float l3 = v.w - __bfloat162float(h1.y);
        __nv_bfloat162 g0 = __floats2bfloat162_rn(l0, l1);
        __nv_bfloat162 g1 = __floats2bfloat162_rn(l2, l3);
        *(__nv_bfloat162*)&Xh[row * X_PITCH + p4]     = h0;
        *(__nv_bfloat162*)&Xh[row * X_PITCH + p4 + 2] = h1;
        *(__nv_bfloat162*)&Xl[row * X_PITCH + p4]     = g0;
        *(__nv_bfloat162*)&Xl[row * X_PITCH + p4 + 2] = g1;
    }
    __syncthreads();

    // ---- mainloop ----
    int lane = tid & 31, wid = tid >> 5;
    int gid = lane >> 2, tig = lane & 3;
    int dbase = (wid & 3) * 32;        // warp m-tile
    int pbase = (wid >> 2) * 64;       // warp n-tile

    uint32_t xh_base = smem_u32(Xh);
    uint32_t xl_base = smem_u32(Xl);
    // ldmatrix x4.trans source rows: groups (k0-7,n0),(k8-15,n0),(k0-7,n0+8),(k8-15,n0+8)
    int lm_off = ((lane & 7) + ((lane >> 3) & 1) * 8) * X_PITCH
               + pbase + ((lane >> 4) & 1) * 8;

    float D[2][8][4];
#pragma unroll
    for (int mf = 0; mf < 2; mf++)
#pragma unroll
        for (int nf = 0; nf < 8; nf++)
#pragma unroll
            for (int q = 0; q < 4; q++) D[mf][nf][q] = 0.f;

#pragma unroll
    for (int ks = 0; ks < 8; ks++) {
        int k0 = ks * 16;
        uint32_t ah[2][4], al[2][4];
#pragma unroll
        for (int mf = 0; mf < 2; mf++) {
            int r0 = dbase + mf * 16 + gid;
            ah[mf][0] = *(const uint32_t*)&Ah[r0 * A_PITCH + k0 + 2 * tig];
            ah[mf][1] = *(const uint32_t*)&Ah[(r0 + 8) * A_PITCH + k0 + 2 * tig];
            ah[mf][2] = *(const uint32_t*)&Ah[r0 * A_PITCH + k0 + 8 + 2 * tig];
            ah[mf][3] = *(const uint32_t*)&Ah[(r0 + 8) * A_PITCH + k0 + 8 + 2 * tig];
            al[mf][0] = *(const uint32_t*)&Al[r0 * A_PITCH + k0 + 2 * tig];
            al[mf][1] = *(const uint32_t*)&Al[(r0 + 8) * A_PITCH + k0 + 2 * tig];
            al[mf][2] = *(const uint32_t*)&Al[r0 * A_PITCH + k0 + 8 + 2 * tig];
            al[mf][3] = *(const uint32_t*)&Al[(r0 + 8) * A_PITCH + k0 + 8 + 2 * tig];
        }
        uint32_t bh[8][2], bl[8][2];
#pragma unroll
        for (int nfp = 0; nfp < 4; nfp++) {
            uint32_t aoff = (uint32_t)(k0 * X_PITCH + lm_off + nfp * 16) * 2;
            ldsm_x4_trans(bh[2 * nfp][0], bh[2 * nfp][1],
                          bh[2 * nfp + 1][0], bh[2 * nfp + 1][1], xh_base + aoff);
            ldsm_x4_trans(bl[2 * nfp][0], bl[2 * nfp][1],
                          bl[2 * nfp + 1][0], bl[2 * nfp + 1][1], xl_base + aoff);
        }
#pragma unroll
        for (int mf = 0; mf < 2; mf++)
#pragma unroll
            for (int nf = 0; nf < 8; nf++) {
                MMA_BF16(D[mf][nf], ah[mf], bh[nf]);
                MMA_BF16(D[mf][nf], ah[mf], bl[nf]);
                MMA_BF16(D[mf][nf], al[mf], bh[nf]);
            }
    }
    __syncthreads();   // all smem reads done; estage/bsm may alias

    // ---- epilogue: restage D; build bias table; fused transform + store ----
#pragma unroll
    for (int mf = 0; mf < 2; mf++)
#pragma unroll
        for (int nf = 0; nf < 8; nf++) {
            float* dd = D[mf][nf];
            int r0 = dbase + mf * 16 + gid;
            int cn = pbase + nf * 8 + 2 * tig;
            float2 v01; v01.x = dd[0]; v01.y = dd[1];
            float2 v23; v23.x = dd[2]; v23.y = dd[3];
            *(float2*)&estage[r0 * A_PITCH + cn] = v01;
            *(float2*)&estage[(r0 + 8) * A_PITCH + cn] = v23;
        }
    for (int i = tid; i < C * K; i += 256) {
        int d = i >> 6, k = i & 63;
        bsm[i] = fmaf(ssm[d], g_adjm[(b * K + k) * C + d], tsm[d]);
    }
    __syncthreads();

    float* ob = out + (size_t)b * C * HW + p0;
#pragma unroll
    for (int i = 0; i < 16; i++) {
        int flat = i * 256 + tid;          // 4096 float4 total
        int row = flat >> 5, c4 = (flat & 31) * 4;
        float4 v = *(float4*)&estage[row * A_PITCH + c4];
        float s = ssm[row];
        const float* brow = bsm + row * 64;
        float4 r;
        r.x = fmaf(s, v.x, brow[sidxp[c4 + 0]]);
        r.y = fmaf(s, v.y, brow[sidxp[c4 + 1]]);
        r.z = fmaf(s, v.z, brow[sidxp[c4 + 2]]);
        r.w = fmaf(s, v.w, brow[sidxp[c4 + 3]]);
        *(float4*)(ob + (size_t)row * HW + c4) = r;
    }
}

// ---------------- launch ----------------
extern "C" void kernel_launch(void* const* d_in, const int* in_sizes, int n_in,
                              void* d_out, int out_size) {
    const float* x        = (const float*)d_in[0];
    const int*   index    = (const int*)d_in[1];
    const float* weight   = (const float*)d_in[2];
    const float* Wm       = (const float*)d_in[3];
    const float* adj_mask = (const float*)d_in[4];
    const float* gamma    = (const float*)d_in[5];
    const float* beta     = (const float*)d_in[6];
    float* out = (float*)d_out;

    cudaFuncSetAttribute(k_pass1,    cudaFuncAttributeMaxDynamicSharedMemorySize, P1_TOTAL);
    cudaFuncSetAttribute(k_gemm_out, cudaFuncAttributeMaxDynamicSharedMemorySize, GSM2_TOTAL);

    k_zero<<<256, 256>>>();
    k_wprep<<<64, 256>>>(weight);
    k_pass1<<<144, 256, P1_TOTAL>>>(x, index);
    kA<<<768, 128>>>(weight, Wm);
    k_Y<<<B * K, 128>>>();
    k_adj<<<B, 256>>>(adj_mask);
    k_bnstats<<<1, 128>>>(gamma, beta);
    k_gemm_out<<<4096, 256, GSM2_TOTAL>>>(x, index, out);
}

// round 10
// speedup vs baseline: 1.1038x; 1.1038x over previous
#include <cuda_runtime.h>
#include <cuda_bf16.h>
#include <cstdint>

#define B 8
#define C 128
#define HW 65536
#define K 64
#define NTOT 524288.0f
#define BN_EPS 1e-5f

// ---------------- scratch (device globals; no allocation allowed) ----------------
__device__ float g_G[C * C];                    // Gram matrix sum_p x x^T
__device__ float g_sums_x[B * K * C];           // segment sums of x
__device__ float g_cnt[B * K];                  // segment counts
__device__ float g_sumsq[C];                    // per-channel sum of xw^2
__device__ float g_means[B * K * C];
__device__ float g_M[C * C];                    // W @ W^T
__device__ float g_Y[B * K * C];                // means @ M
__device__ float g_adj[B * K * K];
__device__ float g_adjm[B * K * C];             // adj_nd @ means
__device__ float g_bias[B * C * K];             // [b][d][k] = s*adjm + t
__device__ float g_s[C];
__device__ float g_t[C];
__device__ __nv_bfloat16 g_wh[C * 132];         // w^T hi  [d][c], pitch 132
__device__ __nv_bfloat16 g_wl[C * 132];         // w^T lo

#define MMA_BF16(d, a, bb) \
    asm volatile("mma.sync.aligned.m16n8k16.row.col.f32.bf16.bf16.f32 " \
        "{%0,%1,%2,%3}, {%4,%5,%6,%7}, {%8,%9}, {%0,%1,%2,%3};" \
        : "+f"((d)[0]), "+f"((d)[1]), "+f"((d)[2]), "+f"((d)[3]) \
        : "r"((a)[0]), "r"((a)[1]), "r"((a)[2]), "r"((a)[3]), \
          "r"((bb)[0]), "r"((bb)[1]))

__device__ __forceinline__ uint32_t smem_u32(const void* p) {
    uint32_t a;
    asm("{ .reg .u64 t; cvta.to.shared.u64 t, %1; cvt.u32.u64 %0, t; }" : "=r"(a) : "l"(p));
    return a;
}
__device__ __forceinline__ void ldsm_x4_trans(uint32_t& r0, uint32_t& r1,
                                              uint32_t& r2, uint32_t& r3, uint32_t addr) {
    asm volatile("ldmatrix.sync.aligned.m8n8.x4.trans.shared.b16 {%0,%1,%2,%3}, [%4];"
                 : "=r"(r0), "=r"(r1), "=r"(r2), "=r"(r3) : "r"(addr));
}

// ---------------- kernel 0: zero accumulators ----------------
__global__ void k_zero() {
    int i = blockIdx.x * blockDim.x + threadIdx.x;
    if (i < B * K * C) g_sums_x[i] = 0.f;
    if (i < C * C)     g_G[i] = 0.f;
    if (i < B * K)     g_cnt[i] = 0.f;
}

// ---------------- kernel 0.5: prep w^T hi/lo ----------------
__global__ void k_wprep(const float* __restrict__ w) {
    int i = blockIdx.x * 256 + threadIdx.x;
    if (i < C * C) {
        int c = i >> 7, d = i & 127;
        float v = w[i];
        __nv_bfloat16 h = __float2bfloat16(v);
        g_wh[d * 132 + c] = h;
        g_wl[d * 132 + c] = __float2bfloat16(v - __bfloat162float(h));
    }
}

// ================= kernel 1: fused stats pass (G, segment sums, counts) =================
// grid 144 (8 b x 18 walkers), 256 threads; each block walks chunks j, j+18, ... (<512)
#define P1_PITCH 132
#define P1_XH 0
#define P1_XL 33792
#define P1_OH 67584
#define P1_TOTAL 84480

__global__ __launch_bounds__(256, 1) void k_pass1(const float* __restrict__ x,
                                                  const int* __restrict__ idx) {
    extern __shared__ char smem[];
    __nv_bfloat16* Xh = (__nv_bfloat16*)(smem + P1_XH);
    __nv_bfloat16* Xl = (__nv_bfloat16*)(smem + P1_XL);
    __nv_bfloat16* OH = (__nv_bfloat16*)(smem + P1_OH);
    __shared__ int   sidx[128];
    __shared__ float hcnt[K];

    int tid = threadIdx.x;
    int b   = blockIdx.x / 18;
    int j   = blockIdx.x % 18;
    int lane = tid & 31, wid = tid >> 5;
    int gid = lane >> 2, tig = lane & 3;
    int dbase  = (wid & 3) * 32;    // G m-tile (rows c1)
    int msbase = (wid & 3) * 16;    // S m-tile (rows k)
    int pbase  = (wid >> 2) * 64;   // n-half (cols c2 / c)

    if (tid < K) hcnt[tid] = 0.f;

    float Dg[2][8][4];
    float Ds[8][4];
#pragma unroll
    for (int mf = 0; mf < 2; mf++)
#pragma unroll
        for (int nf = 0; nf < 8; nf++)
#pragma unroll
            for (int q = 0; q < 4; q++) Dg[mf][nf][q] = 0.f;
#pragma unroll
    for (int nf = 0; nf < 8; nf++)
#pragma unroll
        for (int q = 0; q < 4; q++) Ds[nf][q] = 0.f;

    const float* xb = x + (size_t)b * C * HW;
    const int*   ib = idx + b * HW;

    for (int ch = j; ch < 512; ch += 18) {
        __syncthreads();
        if (tid < 128) sidx[tid] = ib[ch * 128 + tid];
        for (int i = tid; i < 4224; i += 256) ((uint32_t*)OH)[i] = 0u;
        for (int e = tid; e < 4096; e += 256) {
            int row = e >> 5, p4 = (e & 31) * 4;
            float4 v = *(const float4*)(xb + (size_t)row * HW + ch * 128 + p4);
            __nv_bfloat162 h0 = __floats2bfloat162_rn(v.x, v.y);
            __nv_bfloat162 h1 = __floats2bfloat162_rn(v.z, v.w);
            float l0 = v.x - __bfloat162float(h0.x);
            float l1 = v.y - __bfloat162float(h0.y);
            float l2 = v.z - __bfloat162float(h1.x);
            float l3 = v.w - __bfloat162float(h1.y);
            __nv_bfloat162 g0 = __floats2bfloat162_rn(l0, l1);
            __nv_bfloat162 g1 = __floats2bfloat162_rn(l2, l3);
            *(__nv_bfloat162*)&Xh[row * P1_PITCH + p4]     = h0;
            *(__nv_bfloat162*)&Xh[row * P1_PITCH + p4 + 2] = h1;
            *(__nv_bfloat162*)&Xl[row * P1_PITCH + p4]     = g0;
            *(__nv_bfloat162*)&Xl[row * P1_PITCH + p4 + 2] = g1;
        }
        __syncthreads();
        if (tid < 128) {
            int k = sidx[tid];
            OH[k * P1_PITCH + tid] = __float2bfloat16(1.0f);
            atomicAdd(&hcnt[k], 1.f);
        }
        __syncthreads();

#pragma unroll
        for (int ks = 0; ks < 8; ks++) {
            int k0 = ks * 16;
            uint32_t bh[8][2], bl[8][2];
#pragma unroll
            for (int nf = 0; nf < 8; nf++) {
                int cn = pbase + nf * 8 + gid;
                bh[nf][0] = *(const uint32_t*)&Xh[cn * P1_PITCH + k0 + 2 * tig];
                bh[nf][1] = *(const uint32_t*)&Xh[cn * P1_PITCH + k0 + 8 + 2 * tig];
                bl[nf][0] = *(const uint32_t*)&Xl[cn * P1_PITCH + k0 + 2 * tig];
                bl[nf][1] = *(const uint32_t*)&Xl[cn * P1_PITCH + k0 + 8 + 2 * tig];
            }
            uint32_t ah[2][4];
#pragma unroll
            for (int mf = 0; mf < 2; mf++) {
                int r0 = dbase + mf * 16 + gid;
                ah[mf][0] = *(const uint32_t*)&Xh[r0 * P1_PITCH + k0 + 2 * tig];
                ah[mf][1] = *(const uint32_t*)&Xh[(r0 + 8) * P1_PITCH + k0 + 2 * tig];
                ah[mf][2] = *(const uint32_t*)&Xh[r0 * P1_PITCH + k0 + 8 + 2 * tig];
                ah[mf][3] = *(const uint32_t*)&Xh[(r0 + 8) * P1_PITCH + k0 + 8 + 2 * tig];
            }
            uint32_t ao[4];
            {
                int m0 = msbase + gid;
                ao[0] = *(const uint32_t*)&OH[m0 * P1_PITCH + k0 + 2 * tig];
                ao[1] = *(const uint32_t*)&OH[(m0 + 8) * P1_PITCH + k0 + 2 * tig];
                ao[2] = *(const uint32_t*)&OH[m0 * P1_PITCH + k0 + 8 + 2 * tig];
                ao[3] = *(const uint32_t*)&OH[(m0 + 8) * P1_PITCH + k0 + 8 + 2 * tig];
            }
#pragma unroll
            for (int mf = 0; mf < 2; mf++)
#pragma unroll
                for (int nf = 0; nf < 8; nf++)
                    MMA_BF16(Dg[mf][nf], ah[mf], bh[nf]);
#pragma unroll
            for (int nf = 0; nf < 8; nf++) {
                MMA_BF16(Ds[nf], ao, bh[nf]);
                MMA_BF16(Ds[nf], ao, bl[nf]);
            }
        }
    }

    // ---- flush partials ----
#pragma unroll
    for (int mf = 0; mf < 2; mf++)
#pragma unroll
        for (int nf = 0; nf < 8; nf++) {
            int r0 = dbase + mf * 16 + gid;
            int cn = pbase + nf * 8 + 2 * tig;
            atomicAdd(&g_G[r0 * C + cn],           Dg[mf][nf][0]);
            atomicAdd(&g_G[r0 * C + cn + 1],       Dg[mf][nf][1]);
            atomicAdd(&g_G[(r0 + 8) * C + cn],     Dg[mf][nf][2]);
            atomicAdd(&g_G[(r0 + 8) * C + cn + 1], Dg[mf][nf][3]);
        }
#pragma unroll
    for (int nf = 0; nf < 8; nf++) {
        int m0 = msbase + gid;
        int cn = pbase + nf * 8 + 2 * tig;
        atomicAdd(&g_sums_x[(b * K + m0) * C + cn],           Ds[nf][0]);
        atomicAdd(&g_sums_x[(b * K + m0) * C + cn + 1],       Ds[nf][1]);
        atomicAdd(&g_sums_x[(b * K + m0 + 8) * C + cn],       Ds[nf][2]);
        atomicAdd(&g_sums_x[(b * K + m0 + 8) * C + cn + 1],   Ds[nf][3]);
    }
    __syncthreads();
    if (tid < K) atomicAdd(&g_cnt[b * K + tid], hcnt[tid]);
}

// ---------------- kernel A: fused M=WW^T | sumsq=w^T G w | means ----------------
// grid 768, 128 threads: [0,128) M rows; [128,256) sumsq d; [256,768) means bk
__global__ void kA(const float* __restrict__ w, const float* __restrict__ Wm) {
    int blk = blockIdx.x;
    int t = threadIdx.x;
    if (blk < 128) {
        __shared__ float wi[C];
        int i = blk;
        wi[t] = Wm[i * C + t];
        __syncthreads();
        float acc = 0.f;
#pragma unroll 8
        for (int c = 0; c < C; c++) acc += wi[c] * Wm[t * C + c];
        g_M[i * C + t] = acc;
    } else if (blk < 256) {
        __shared__ float wcol[C];
        __shared__ float red[C];
        int d = blk - 128;
        wcol[t] = w[t * C + d];
        __syncthreads();
        float acc = 0.f;
#pragma unroll 8
        for (int c2 = 0; c2 < C; c2++) acc += g_G[t * C + c2] * wcol[c2];
        red[t] = acc * wcol[t];
        __syncthreads();
        for (int s = 64; s > 0; s >>= 1) {
            if (t < s) red[t] += red[t + s];
            __syncthreads();
        }
        if (t == 0) g_sumsq[d] = red[0];
    } else {
        __shared__ float s[C];
        int bk = blk - 256;
        s[t] = g_sums_x[bk * C + t];
        __syncthreads();
        float cnt = g_cnt[bk];
        float denom = (cnt == 0.f) ? 1.f : cnt;
        float acc = 0.f;
#pragma unroll 8
        for (int c = 0; c < C; c++) acc += s[c] * w[c * C + t];
        g_means[bk * C + t] = acc / denom;
    }
}

// ---------------- kernel 5: Y[b,k,d] = means[b,k,:] @ M ----------------
__global__ void k_Y() {
    __shared__ float ms[C];
    int bk = blockIdx.x;
    int d = threadIdx.x;
    ms[d] = g_means[bk * C + d];
    __syncthreads();
    float acc = 0.f;
#pragma unroll 8
    for (int c = 0; c < C; c++) acc += ms[c] * g_M[c * C + d];
    g_Y[bk * C + d] = acc;
}

// ---------------- kernel 6: adjacency + adj_means ----------------
__global__ __launch_bounds__(256) void k_adj(const float* __restrict__ adj_mask) {
    __shared__ float msm[K][C + 1];
    __shared__ float gq[K];
    int b = blockIdx.x, tid = threadIdx.x;
    const float* mb = g_means + b * K * C;
    const float* yb = g_Y + b * K * C;

    for (int i = tid; i < K * C; i += 256) msm[i >> 7][i & 127] = mb[i];
    __syncthreads();

    if (tid < K) {
        float a = 0.f;
#pragma unroll 8
        for (int d = 0; d < C; d++) a += yb[tid * C + d] * msm[tid][d];
        gq[tid] = a;
    }
    __syncthreads();

    for (int i = tid; i < K * K; i += 256) {
        int p = i >> 6, q = i & 63;
        float dot = 0.f;
#pragma unroll 8
        for (int d = 0; d < C; d++) dot += yb[p * C + d] * msm[q][d];
        float quad = gq[p] + gq[q] - 2.f * dot;
        g_adj[b * K * K + i] = (p == q) ? 0.f : expf(-quad) * adj_mask[i];
    }
    __syncthreads();

    for (int i = tid; i < K * C; i += 256) {
        int p = i >> 7, d = i & 127;
        const float* arow = g_adj + b * K * K + p * K;
        float acc = 0.f;
#pragma unroll 8
        for (int q = 0; q < K; q++) acc += arow[q] * msm[q][d];
        g_adjm[b * K * C + i] = acc;
    }
}

// ---------------- kernel 7: BN statistics (analytic) ----------------
__global__ void k_bnstats(const float* __restrict__ gamma, const float* __restrict__ beta) {
    int d = threadIdx.x;
    float S1 = 0.f, S2 = 0.f;
    for (int bk = 0; bk < B * K; bk++) {
        float cnt = g_cnt[bk];
        float denom = (cnt == 0.f) ? 1.f : cnt;
        float m = g_means[bk * C + d];
        float am = g_adjm[bk * C + d];
        float sxw = m * denom;
        S1 += sxw + cnt * am;
        S2 += 2.f * am * sxw + cnt * am * am;
    }
    S2 += g_sumsq[d];
    float mu = S1 / NTOT;
    float var = S2 / NTOT - mu * mu;
    float s = gamma[d] * rsqrtf(var + BN_EPS);
    g_s[d] = s;
    g_t[d] = beta[d] - mu * s;
}

// ---------------- kernel 8: bias table bias[b][d][k] = s[d]*adjm[b][k][d] + t[d] ----------------
__global__ void k_bias() {
    int b = blockIdx.x;
    for (int i = threadIdx.x; i < C * K; i += 256) {
        int d = i >> 6, k = i & 63;
        g_bias[b * C * K + i] = fmaf(g_s[d], g_adjm[(b * K + k) * C + d], g_t[d]);
    }
}

// ================= kernel 9: fused GEMM + output (ldmatrix.trans path) =================
// out[b,d,p] = s[d] * (x @ weight)[b,d,p] + bias[b,d,idx[p]]
#define A_PITCH 132
#define X_PITCH 136
#define GSM2_AH 0
#define GSM2_AL 33792
#define GSM2_XH 67584
#define GSM2_XL 102400
#define GSM2_TOTAL 137216

__global__ __launch_bounds__(256, 1) void k_gemm_out(const float* __restrict__ x,
                                                     const int* __restrict__ idx,
                                                     float* __restrict__ out) {
    extern __shared__ char smem[];
    __nv_bfloat16* Ah = (__nv_bfloat16*)(smem + GSM2_AH);
    __nv_bfloat16* Al = (__nv_bfloat16*)(smem + GSM2_AL);
    __nv_bfloat16* Xh = (__nv_bfloat16*)(smem + GSM2_XH);
    __nv_bfloat16* Xl = (__nv_bfloat16*)(smem + GSM2_XL);
    float* estage = (float*)smem;                 // epilogue alias over Ah+Al (67584 B)
    float* bsm    = (float*)(smem + GSM2_XH);     // epilogue alias over Xh (32768 B used)
    __shared__ float ssm[C];
    __shared__ int   sidxp[128];

    int tid = threadIdx.x;
    int b = blockIdx.x >> 9;
    int p0 = (blockIdx.x & 511) << 7;
    const float* xb = x + (size_t)b * C * HW + p0;

    if (tid < 128) sidxp[tid] = idx[b * HW + p0 + tid];
    if (tid < C) ssm[tid] = g_s[tid];

    // ---- copy prepped W hi/lo ----
    {
        const uint32_t* wh32 = (const uint32_t*)g_wh;
        const uint32_t* wl32 = (const uint32_t*)g_wl;
        uint32_t* ah32 = (uint32_t*)Ah;
        uint32_t* al32 = (uint32_t*)Al;
        for (int i = tid; i < 8448; i += 256) { ah32[i] = wh32[i]; al32[i] = wl32[i]; }
    }
    // ---- convert x -> [c][p] bf16 hi/lo (coalesced both sides, no transpose) ----
    for (int e = tid; e < 4096; e += 256) {
        int row = e >> 5, p4 = (e & 31) * 4;
        float4 v = *(const float4*)(xb + (size_t)row * HW + p4);
        __nv_bfloat162 h0 = __floats2bfloat162_rn(v.x, v.y);
        __nv_bfloat162 h1 = __floats2bfloat162_rn(v.z, v.w);
        float l0 = v.x - __bfloat162float(h0.x);
        float l1 = v.y - __bfloat162float(h0.y);
        float l2 = v.z - __bfloat162float(h1.x);
        float l3 = v.w - __bfloat162float(h1.y);
        __nv_bfloat162 g0 = __floats2bfloat162_rn(l0, l1);
        __nv_bfloat162 g1 = __floats2bfloat162_rn(l2, l3);
        *(__nv_bfloat162*)&Xh[row * X_PITCH + p4]     = h0;
        *(__nv_bfloat162*)&Xh[row * X_PITCH + p4 + 2] = h1;
        *(__nv_bfloat162*)&Xl[row * X_PITCH + p4]     = g0;
        *(__nv_bfloat162*)&Xl[row * X_PITCH + p4 + 2] = g1;
    }
    __syncthreads();

    // ---- mainloop ----
    int lane = tid & 31, wid = tid >> 5;
    int gid = lane >> 2, tig = lane & 3;
    int dbase = (wid & 3) * 32;        // warp m-tile
    int pbase = (wid >> 2) * 64;       // warp n-tile

    uint32_t xh_base = smem_u32(Xh);
    uint32_t xl_base = smem_u32(Xl);
    // ldmatrix x4.trans source rows: groups (k0-7,n0),(k8-15,n0),(k0-7,n0+8),(k8-15,n0+8)
    int lm_off = ((lane & 7) + ((lane >> 3) & 1) * 8) * X_PITCH
               + pbase + ((lane >> 4) & 1) * 8;

    float D[2][8][4];
#pragma unroll
    for (int mf = 0; mf < 2; mf++)
#pragma unroll
        for (int nf = 0; nf < 8; nf++)
#pragma unroll
            for (int q = 0; q < 4; q++) D[mf][nf][q] = 0.f;

#pragma unroll
    for (int ks = 0; ks < 8; ks++) {
        int k0 = ks * 16;
        uint32_t ah[2][4], al[2][4];
#pragma unroll
        for (int mf = 0; mf < 2; mf++) {
            int r0 = dbase + mf * 16 + gid;
            ah[mf][0] = *(const uint32_t*)&Ah[r0 * A_PITCH + k0 + 2 * tig];
            ah[mf][1] = *(const uint32_t*)&Ah[(r0 + 8) * A_PITCH + k0 + 2 * tig];
            ah[mf][2] = *(const uint32_t*)&Ah[r0 * A_PITCH + k0 + 8 + 2 * tig];
            ah[mf][3] = *(const uint32_t*)&Ah[(r0 + 8) * A_PITCH + k0 + 8 + 2 * tig];
            al[mf][0] = *(const uint32_t*)&Al[r0 * A_PITCH + k0 + 2 * tig];
            al[mf][1] = *(const uint32_t*)&Al[(r0 + 8) * A_PITCH + k0 + 2 * tig];
            al[mf][2] = *(const uint32_t*)&Al[r0 * A_PITCH + k0 + 8 + 2 * tig];
            al[mf][3] = *(const uint32_t*)&Al[(r0 + 8) * A_PITCH + k0 + 8 + 2 * tig];
        }
        uint32_t bh[8][2], bl[8][2];
#pragma unroll
        for (int nfp = 0; nfp < 4; nfp++) {
            uint32_t aoff = (uint32_t)(k0 * X_PITCH + lm_off + nfp * 16) * 2;
            ldsm_x4_trans(bh[2 * nfp][0], bh[2 * nfp][1],
                          bh[2 * nfp + 1][0], bh[2 * nfp + 1][1], xh_base + aoff);
            ldsm_x4_trans(bl[2 * nfp][0], bl[2 * nfp][1],
                          bl[2 * nfp + 1][0], bl[2 * nfp + 1][1], xl_base + aoff);
        }
#pragma unroll
        for (int mf = 0; mf < 2; mf++)
#pragma unroll
            for (int nf = 0; nf < 8; nf++) {
                MMA_BF16(D[mf][nf], ah[mf], bh[nf]);
                MMA_BF16(D[mf][nf], ah[mf], bl[nf]);
                MMA_BF16(D[mf][nf], al[mf], bh[nf]);
            }
    }
    __syncthreads();   // all smem reads done; estage/bsm may alias

    // ---- epilogue: restage D; load precomputed bias (contiguous); transform + store ----
#pragma unroll
    for (int mf = 0; mf < 2; mf++)
#pragma unroll
        for (int nf = 0; nf < 8; nf++) {
            float* dd = D[mf][nf];
            int r0 = dbase + mf * 16 + gid;
            int cn = pbase + nf * 8 + 2 * tig;
            float2 v01; v01.x = dd[0]; v01.y = dd[1];
            float2 v23; v23.x = dd[2]; v23.y = dd[3];
            *(float2*)&estage[r0 * A_PITCH + cn] = v01;
            *(float2*)&estage[(r0 + 8) * A_PITCH + cn] = v23;
        }
    {
        const float4* gb = (const float4*)(g_bias + b * C * K);
        float4* bs4 = (float4*)bsm;
        for (int i = tid; i < 2048; i += 256) bs4[i] = gb[i];
    }
    __syncthreads();

    float* ob = out + (size_t)b * C * HW + p0;
#pragma unroll
    for (int i = 0; i < 16; i++) {
        int flat = i * 256 + tid;          // 4096 float4 total
        int row = flat >> 5, c4 = (flat & 31) * 4;
        float4 v = *(float4*)&estage[row * A_PITCH + c4];
        float s = ssm[row];
        const float* brow = bsm + row * 64;
        float4 r;
        r.x = fmaf(s, v.x, brow[sidxp[c4 + 0]]);
        r.y = fmaf(s, v.y, brow[sidxp[c4 + 1]]);
        r.z = fmaf(s, v.z, brow[sidxp[c4 + 2]]);
        r.w = fmaf(s, v.w, brow[sidxp[c4 + 3]]);
        *(float4*)(ob + (size_t)row * HW + c4) = r;
    }
}

// ---------------- launch ----------------
extern "C" void kernel_launch(void* const* d_in, const int* in_sizes, int n_in,
                              void* d_out, int out_size) {
    const float* x        = (const float*)d_in[0];
    const int*   index    = (const int*)d_in[1];
    const float* weight   = (const float*)d_in[2];
    const float* Wm       = (const float*)d_in[3];
    const float* adj_mask = (const float*)d_in[4];
    const float* gamma    = (const float*)d_in[5];
    const float* beta     = (const float*)d_in[6];
    float* out = (float*)d_out;

    cudaFuncSetAttribute(k_pass1,    cudaFuncAttributeMaxDynamicSharedMemorySize, P1_TOTAL);
    cudaFuncSetAttribute(k_gemm_out, cudaFuncAttributeMaxDynamicSharedMemorySize, GSM2_TOTAL);

    k_zero<<<256, 256>>>();
    k_wprep<<<64, 256>>>(weight);
    k_pass1<<<144, 256, P1_TOTAL>>>(x, index);
    kA<<<768, 128>>>(weight, Wm);
    k_Y<<<B * K, 128>>>();
    k_adj<<<B, 256>>>(adj_mask);
    k_bnstats<<<1, 128>>>(gamma, beta);
    k_bias<<<B, 256>>>();
    k_gemm_out<<<4096, 256, GSM2_TOTAL>>>(x, index, out);
}